// round 2
// baseline (speedup 1.0000x reference)
#include <cuda_runtime.h>
#include <math.h>

#define PI_F 3.14159265358979323846

// Tiled affine crop: one block = one 32x32 output tile of one batch image.
// Stage the input bounding box for all 3 channels into shared memory
// (coalesced), then bilinear-gather from smem.
//
// Since c = cos/(|cos|+|sin|), s = sin/(|cos|+|sin|), we have |c|+|s| = 1,
// so the input-space span of a TILE-wide output tile is exactly TILE*W/S
// per axis (~74 px for W=512, S=224) -> fits in an 80x80 smem tile.

constexpr int TILE  = 32;
constexpr int BLOCK = 512;     // 2 output pixels per thread
constexpr int MAXW  = 80;      // max staged region height/width
constexpr int SMW   = 81;      // smem row stride (odd, spreads banks)
constexpr int CHS   = MAXW * SMW;  // per-channel smem floats

__global__ void __launch_bounds__(BLOCK, 2) affine_tile_kernel(
    const float* __restrict__ x,      // [B, 3, H, W]
    const float* __restrict__ angles, // [B]
    float* __restrict__ out,          // [B, 3, S, S]
    int H, int W, int S, int ntx)
{
    extern __shared__ float sm[];    // [3][MAXW][SMW]

    const int b  = blockIdx.y;
    const int t  = blockIdx.x;
    const int tx = t % ntx;
    const int ty = t / ntx;
    const int ox0 = tx * TILE;
    const int oy0 = ty * TILE;

    // Rotation params (identical arithmetic to the reference).
    const float rad = angles[b] * (float)(PI_F / 180.0);
    float sn, cs;
    sincosf(rad, &sn, &cs);
    const float scale = fabsf(cs) + fabsf(sn);
    const float c = cs / scale;
    const float s = sn / scale;

    const float stepx = 2.0f / (float)S;

    // Input-space coordinate of output pixel (ox, oy) — same chain as reference.
    auto coord = [&](int ox, int oy, float& ix, float& iy) {
        float xs = ((float)ox + 0.5f) * stepx - 1.0f;
        float ys = ((float)oy + 0.5f) * stepx - 1.0f;
        float gx = c * xs - s * ys;
        float gy = s * xs + c * ys;
        ix = ((gx + 1.0f) * (float)W - 1.0f) * 0.5f;
        iy = ((gy + 1.0f) * (float)H - 1.0f) * 0.5f;
    };

    // Bounding box from the 4 tile corners (coords are linear in ox, oy);
    // widen by 1 px each side as fp-safety margin, +1 for the x0+1 sample.
    float ixa, iya, ixb, iyb, ixc, iyc, ixd, iyd;
    coord(ox0,          oy0,          ixa, iya);
    coord(ox0 + TILE-1, oy0,          ixb, iyb);
    coord(ox0,          oy0 + TILE-1, ixc, iyc);
    coord(ox0 + TILE-1, oy0 + TILE-1, ixd, iyd);
    float min_ix = fminf(fminf(ixa, ixb), fminf(ixc, ixd));
    float max_ix = fmaxf(fmaxf(ixa, ixb), fmaxf(ixc, ixd));
    float min_iy = fminf(fminf(iya, iyb), fminf(iyc, iyd));
    float max_iy = fmaxf(fmaxf(iya, iyb), fmaxf(iyc, iyd));

    const int x_lo = max(0, (int)floorf(min_ix) - 1);
    const int x_hi = min(W - 1, (int)floorf(max_ix) + 2);
    const int y_lo = max(0, (int)floorf(min_iy) - 1);
    const int y_hi = min(H - 1, (int)floorf(max_iy) + 2);
    const int rw = x_hi - x_lo + 1;
    const int rh = y_hi - y_lo + 1;

    const bool fits = (rw <= MAXW) && (rh <= MAXW) && (rw > 0) && (rh > 0);

    const int tid  = threadIdx.x;
    const int oxl  = tid & (TILE - 1);
    const int oyl0 = tid >> 5;           // 0..15

    if (fits) {
        // ---- Stage all 3 channel bboxes into smem (coalesced) ----
        const int n = rh * rw;
        #pragma unroll
        for (int ch = 0; ch < 3; ++ch) {
            const float* src = x + ((long long)(b * 3 + ch) * H + y_lo) * W + x_lo;
            float* dst = sm + ch * CHS;
            for (int i = tid; i < n; i += BLOCK) {
                int r   = i / rw;
                int col = i - r * rw;
                dst[r * SMW + col] = __ldg(src + (long long)r * W + col);
            }
        }
        __syncthreads();
    }

    #pragma unroll
    for (int k = 0; k < 2; ++k) {
        const int oy = oy0 + oyl0 + k * 16;
        const int ox = ox0 + oxl;
        if (ox >= S || oy >= S) continue;

        float ix, iy;
        coord(ox, oy, ix, iy);

        const float x0f = floorf(ix);
        const float y0f = floorf(iy);
        const int x0 = (int)x0f;
        const int y0 = (int)y0f;
        const int x1 = x0 + 1;
        const int y1 = y0 + 1;

        const float wx1 = ix - x0f;
        const float wx0 = 1.0f - wx1;
        const float wy1 = iy - y0f;
        const float wy0 = 1.0f - wy1;

        const bool inx0 = (x0 >= 0) & (x0 < W);
        const bool inx1 = (x1 >= 0) & (x1 < W);
        const bool iny0 = (y0 >= 0) & (y0 < H);
        const bool iny1 = (y1 >= 0) & (y1 < H);

        const float w00 = (inx0 & iny0) ? (wy0 * wx0) : 0.0f;
        const float w01 = (inx1 & iny0) ? (wy0 * wx1) : 0.0f;
        const float w10 = (inx0 & iny1) ? (wy1 * wx0) : 0.0f;
        const float w11 = (inx1 & iny1) ? (wy1 * wx1) : 0.0f;

        const int x0c = min(max(x0, 0), W - 1);
        const int x1c = min(max(x1, 0), W - 1);
        const int y0c = min(max(y0, 0), H - 1);
        const int y1c = min(max(y1, 0), H - 1);

        if (fits) {
            // Local smem offsets: all clamped coords provably lie in the bbox.
            const int o00 = (y0c - y_lo) * SMW + (x0c - x_lo);
            const int o01 = (y0c - y_lo) * SMW + (x1c - x_lo);
            const int o10 = (y1c - y_lo) * SMW + (x0c - x_lo);
            const int o11 = (y1c - y_lo) * SMW + (x1c - x_lo);

            #pragma unroll
            for (int ch = 0; ch < 3; ++ch) {
                const float* tch = sm + ch * CHS;
                float v = w00 * tch[o00] + w01 * tch[o01]
                        + w10 * tch[o10] + w11 * tch[o11];
                out[((long long)(b * 3 + ch) * S + oy) * S + ox] = v;
            }
        } else {
            // Fallback: direct global gather (any shape).
            const long long i00 = (long long)y0c * W + x0c;
            const long long i01 = (long long)y0c * W + x1c;
            const long long i10 = (long long)y1c * W + x0c;
            const long long i11 = (long long)y1c * W + x1c;
            const long long HW = (long long)H * W;
            const float* img = x + (long long)b * 3 * HW;
            #pragma unroll
            for (int ch = 0; ch < 3; ++ch) {
                const float* p = img + (long long)ch * HW;
                float v = w00 * __ldg(p + i00) + w01 * __ldg(p + i01)
                        + w10 * __ldg(p + i10) + w11 * __ldg(p + i11);
                out[((long long)(b * 3 + ch) * S + oy) * S + ox] = v;
            }
        }
    }
}

extern "C" void kernel_launch(void* const* d_in, const int* in_sizes, int n_in,
                              void* d_out, int out_size)
{
    const float* x = (const float*)d_in[0];
    const float* angles = (const float*)d_in[1];
    float* out = (float*)d_out;

    const int B = in_sizes[1];
    const int C = 3;
    const long long hw = (long long)in_sizes[0] / ((long long)B * C);
    const int H = (int)(sqrt((double)hw) + 0.5);
    const int W = H;
    const long long ss = (long long)out_size / ((long long)B * C);
    const int S = (int)(sqrt((double)ss) + 0.5);

    const int ntx = (S + TILE - 1) / TILE;
    const int nty = (S + TILE - 1) / TILE;

    const size_t smem = 3 * CHS * sizeof(float);  // 77,760 B
    cudaFuncSetAttribute(affine_tile_kernel,
                         cudaFuncAttributeMaxDynamicSharedMemorySize, (int)smem);

    dim3 grid(ntx * nty, B, 1);
    affine_tile_kernel<<<grid, BLOCK, smem>>>(x, angles, out, H, W, S, ntx);
}